// round 1
// baseline (speedup 1.0000x reference)
#include <cuda_runtime.h>
#include <cuda_bf16.h>
#include <math.h>

#define NC   6
#define NH   8
#define NL   3
#define NPT  8
#define CDIM 256
#define DDIM 32
#define NQ   6400
#define STOT 14784   // 64*176 + 32*88 + 16*44

// ---------------- scratch (device globals; no allocations allowed) ----------
__device__ float g_inv [NC * 16];
__device__ float g_coor[NC * NQ * 2];
__device__ float g_mask[NC * NQ];
__device__ float g_off [NQ * 384];
__device__ float g_attn[NQ * 192];
__device__ float g_value[(size_t)NC * NH * STOT * DDIM];  // 90.8 MB, [cam][head][s][d]
__device__ float g_slots[NQ * CDIM];

// ---------------- 4x4 inverse of cam2ego (6 matrices) -----------------------
__global__ void k_inv(const float* __restrict__ cam2ego) {
    int c = threadIdx.x;
    if (c >= NC) return;
    float a[4][8];
    for (int r = 0; r < 4; r++)
        for (int j = 0; j < 4; j++) {
            a[r][j]     = cam2ego[c * 16 + r * 4 + j];
            a[r][4 + j] = (r == j) ? 1.f : 0.f;
        }
    for (int col = 0; col < 4; col++) {
        int piv = col; float mx = fabsf(a[col][col]);
        for (int r = col + 1; r < 4; r++) {
            float v = fabsf(a[r][col]);
            if (v > mx) { mx = v; piv = r; }
        }
        if (piv != col)
            for (int j = 0; j < 8; j++) { float t = a[col][j]; a[col][j] = a[piv][j]; a[piv][j] = t; }
        float inv = 1.f / a[col][col];
        for (int j = 0; j < 8; j++) a[col][j] *= inv;
        for (int r = 0; r < 4; r++) if (r != col) {
            float f = a[r][col];
            for (int j = 0; j < 8; j++) a[r][j] -= f * a[col][j];
        }
    }
    for (int r = 0; r < 4; r++)
        for (int j = 0; j < 4; j++)
            g_inv[c * 16 + r * 4 + j] = a[r][4 + j];
}

// ---------------- projection: coor + mask per (cam, q) ----------------------
__global__ void k_proj(const float* __restrict__ means,
                       const float* __restrict__ intrins,
                       const float* __restrict__ post_rots,
                       const float* __restrict__ post_trans) {
    int idx = blockIdx.x * blockDim.x + threadIdx.x;
    if (idx >= NC * NQ) return;
    int cam = idx / NQ, q = idx % NQ;
    float mx = means[q * 3 + 0], my = means[q * 3 + 1], mz = means[q * 3 + 2];
    const float* M = g_inv + cam * 16;
    float X = M[0] * mx + M[1] * my + M[2]  * mz + M[3];
    float Y = M[4] * mx + M[5] * my + M[6]  * mz + M[7];
    float Z = M[8] * mx + M[9] * my + M[10] * mz + M[11];
    const float* I = intrins + cam * 9;
    float u  = I[0] * X + I[1] * Y + I[2] * Z;
    float v  = I[3] * X + I[4] * Y + I[5] * Z;
    float zz = I[6] * X + I[7] * Y + I[8] * Z;
    float iz = 1.f / (zz + 1e-4f);
    float m0 = u * iz, m1 = v * iz, m2 = zz;
    const float* P = post_rots + cam * 9;
    const float* T = post_trans + cam * 3;
    float px = P[0] * m0 + P[1] * m1 + P[2] * m2 + T[0];
    float py = P[3] * m0 + P[4] * m1 + P[5] * m2 + T[1];
    float pz = P[6] * m0 + P[7] * m1 + P[8] * m2 + T[2];
    float cx = px / 1408.0f;
    float cy = py / 512.0f;
    bool msk = (pz > 0.01f) && (cx > 0.f) && (cx < 1.f) && (cy > 0.f) && (cy < 1.f);
    g_coor[idx * 2 + 0] = cx;
    g_coor[idx * 2 + 1] = cy;
    g_mask[idx] = msk ? 1.f : 0.f;
}

// ---------------- offsets + attn logits GEMM: (6400,256)@(256,576) ----------
__global__ void k_offattn(const float* __restrict__ feature,
                          const float* __restrict__ W_off, const float* __restrict__ b_off,
                          const float* __restrict__ W_attn, const float* __restrict__ b_attn) {
    __shared__ float xs[CDIM * 16];   // [c][k]
    int q0 = blockIdx.x * 16;
    int tid = threadIdx.x;
    // transposed load (STS conflicts here are cheap, one-time)
    for (int k = 0; k < 16; k++)
        xs[tid * 16 + k] = feature[(q0 + k) * CDIM + tid];
    __syncthreads();

    int col0 = tid;         // 0..255   -> W_off
    int col1 = tid + 256;   // 256..511 -> W_off if <384 else W_attn
    int col2 = tid + 512;   // 512..575 -> W_attn (valid tid<64)
    const float* p0 = W_off + col0;
    const float* p1; int st1; float bias1;
    if (col1 < 384) { p1 = W_off + col1;        st1 = 384; bias1 = b_off[col1]; }
    else            { p1 = W_attn + (col1-384); st1 = 192; bias1 = b_attn[col1-384]; }
    bool has2 = (tid < 64);
    const float* p2 = W_attn + (has2 ? (col2 - 384) : 0);
    float bias2 = has2 ? b_attn[col2 - 384] : 0.f;
    float bias0 = b_off[col0];

    float a0[16], a1[16], a2[16];
#pragma unroll
    for (int k = 0; k < 16; k++) { a0[k] = bias0; a1[k] = bias1; a2[k] = bias2; }

    for (int c = 0; c < CDIM; c++) {
        float w0 = p0[c * 384];
        float w1 = p1[c * st1];
        float w2 = p2[c * 192];
        const float4* xc = (const float4*)&xs[c * 16];
#pragma unroll
        for (int k4 = 0; k4 < 4; k4++) {
            float4 x = xc[k4];
            a0[k4*4+0] += x.x * w0; a0[k4*4+1] += x.y * w0; a0[k4*4+2] += x.z * w0; a0[k4*4+3] += x.w * w0;
            a1[k4*4+0] += x.x * w1; a1[k4*4+1] += x.y * w1; a1[k4*4+2] += x.z * w1; a1[k4*4+3] += x.w * w1;
            a2[k4*4+0] += x.x * w2; a2[k4*4+1] += x.y * w2; a2[k4*4+2] += x.z * w2; a2[k4*4+3] += x.w * w2;
        }
    }
#pragma unroll
    for (int k = 0; k < 16; k++) {
        int q = q0 + k;
        g_off[q * 384 + col0] = a0[k];
        if (col1 < 384) g_off[q * 384 + col1] = a1[k];
        else            g_attn[q * 192 + (col1 - 384)] = a1[k];
        if (has2)       g_attn[q * 192 + (col2 - 384)] = a2[k];
    }
}

// ---------------- softmax over 24 per (q, head), in place -------------------
__global__ void k_softmax() {
    int i = blockIdx.x * blockDim.x + threadIdx.x;
    if (i >= NQ * NH) return;
    float* p = g_attn + (i / NH) * 192 + (i % NH) * 24;
    float mx = -1e30f;
    for (int j = 0; j < 24; j++) mx = fmaxf(mx, p[j]);
    float s = 0.f;
    for (int j = 0; j < 24; j++) s += expf(p[j] - mx);
    float inv = 1.f / s;
    for (int j = 0; j < 24; j++) p[j] = expf(p[j] - mx) * inv;
}

// ---------------- value build + GEMM: (6*14784,256)@(256,256) ---------------
// output layout g_value[cam][head][s][d]
__global__ void k_value(const float* __restrict__ feat0,
                        const float* __restrict__ feat1,
                        const float* __restrict__ feat2,
                        const float* __restrict__ W_val, const float* __restrict__ b_val,
                        const float* __restrict__ ce,    const float* __restrict__ le) {
    __shared__ float As[32 * 64];
    __shared__ float Bs[32 * 64];
    __shared__ float es[CDIM];

    int bx  = blockIdx.x;           // 0..1385
    int cam = bx / 231;
    int rb  = bx % 231;
    int lvl = (rb < 176) ? 0 : ((rb < 220) ? 1 : 2);
    int m0  = rb * 64;
    int hw, pix0; const float* fb;
    if (lvl == 0)      { hw = 11264; pix0 = m0;          fb = feat0; }
    else if (lvl == 1) { hw = 2816;  pix0 = m0 - 11264;  fb = feat1; }
    else               { hw = 704;   pix0 = m0 - 14080;  fb = feat2; }
    fb += (size_t)cam * CDIM * hw;
    int n0  = blockIdx.y * 64;
    int tid = threadIdx.x;

    es[tid] = ce[cam * CDIM + tid] + le[lvl * CDIM + tid];
    __syncthreads();

    int mm = tid & 63, kb = tid >> 6;     // loader mapping
    int ty = tid >> 4, tx = tid & 15;     // compute mapping (4x4 tile)

    float acc[4][4];
#pragma unroll
    for (int j = 0; j < 4; j++) {
        float b = b_val[n0 + tx * 4 + j];
#pragma unroll
        for (int i = 0; i < 4; i++) acc[i][j] = b;
    }

    for (int kt = 0; kt < 8; kt++) {
#pragma unroll
        for (int j = 0; j < 8; j++) {
            int k = kb * 8 + j;
            int c = kt * 32 + k;
            As[k * 64 + mm] = fb[(size_t)c * hw + pix0 + mm] + es[c];
            Bs[k * 64 + mm] = W_val[c * CDIM + n0 + mm];
        }
        __syncthreads();
#pragma unroll
        for (int k = 0; k < 32; k++) {
            float4 av = *(const float4*)&As[k * 64 + ty * 4];
            float4 bv = *(const float4*)&Bs[k * 64 + tx * 4];
            acc[0][0] += av.x * bv.x; acc[0][1] += av.x * bv.y; acc[0][2] += av.x * bv.z; acc[0][3] += av.x * bv.w;
            acc[1][0] += av.y * bv.x; acc[1][1] += av.y * bv.y; acc[1][2] += av.y * bv.z; acc[1][3] += av.y * bv.w;
            acc[2][0] += av.z * bv.x; acc[2][1] += av.z * bv.y; acc[2][2] += av.z * bv.z; acc[2][3] += av.z * bv.w;
            acc[3][0] += av.w * bv.x; acc[3][1] += av.w * bv.y; acc[3][2] += av.w * bv.z; acc[3][3] += av.w * bv.w;
        }
        __syncthreads();
    }
    // write: n = n0 + tx*4 + j ; head = n>>5, d = n&31 (same head across j)
    int nbase = n0 + tx * 4;
    int hh = nbase >> 5;
    int d  = nbase & 31;
#pragma unroll
    for (int i = 0; i < 4; i++) {
        int s = m0 + ty * 4 + i;
        float4 vv = make_float4(acc[i][0], acc[i][1], acc[i][2], acc[i][3]);
        *(float4*)&g_value[(((size_t)cam * NH + hh) * STOT + s) * DDIM + d] = vv;
    }
}

// ---------------- MSDA sampler: one block per query, one warp per head ------
__global__ void k_sampler() {
    __shared__ float s_off[384];
    __shared__ float s_attn[192];
    __shared__ float s_coor[12];
    __shared__ float s_mask[6];
    int q = blockIdx.x, tid = threadIdx.x;

    s_off[tid] = g_off[q * 384 + tid];
    if (tid < 128) s_off[tid + 256] = g_off[q * 384 + tid + 256];
    if (tid < 192) s_attn[tid] = g_attn[q * 192 + tid];
    if (tid < 12) {
        int cam = tid >> 1, xy = tid & 1;
        s_coor[tid] = g_coor[(cam * NQ + q) * 2 + xy];
    }
    if (tid < 6) s_mask[tid] = g_mask[tid * NQ + q];
    __syncthreads();

    int h = tid >> 5, lane = tid & 31;
    float cnt = 0.f;
#pragma unroll
    for (int c = 0; c < 6; c++) cnt += s_mask[c];

    const int lw[3]  = {176, 88, 44};
    const int lhh[3] = {64, 32, 16};
    const int lst[3] = {0, 11264, 14080};

    float acc = 0.f;
    for (int cam = 0; cam < NC; cam++) {
        float m = s_mask[cam];
        if (m == 0.f) continue;
        float cx = s_coor[cam * 2], cy = s_coor[cam * 2 + 1];
        const float* vcam = g_value + ((size_t)(cam * NH + h)) * STOT * DDIM + lane;
#pragma unroll
        for (int lvl = 0; lvl < 3; lvl++) {
            int w = lw[lvl], hh2 = lhh[lvl];
            const float* vb = vcam + (size_t)lst[lvl] * DDIM;
            float bx = cx * (float)w   - 0.5f;
            float by = cy * (float)hh2 - 0.5f;
#pragma unroll
            for (int p = 0; p < NPT; p++) {
                int oi = ((h * 3 + lvl) * 8 + p) * 2;
                float x = bx + s_off[oi];
                float y = by + s_off[oi + 1];
                float a = s_attn[h * 24 + lvl * 8 + p] * m;
                float xf = floorf(x), yf = floorf(y);
                float tx = x - xf, ty = y - yf;
                int x0 = (int)xf, y0 = (int)yf;
                bool vx0 = (x0 >= 0) && (x0 <= w - 1);
                bool vx1 = (x0 + 1 >= 0) && (x0 + 1 <= w - 1);
                bool vy0 = (y0 >= 0) && (y0 <= hh2 - 1);
                bool vy1 = (y0 + 1 >= 0) && (y0 + 1 <= hh2 - 1);
                float w00 = a * (1.f - tx) * (1.f - ty);
                float w10 = a * tx * (1.f - ty);
                float w01 = a * (1.f - tx) * ty;
                float w11 = a * tx * ty;
                if (vy0) {
                    int r = y0 * w;
                    if (vx0) acc += w00 * vb[(r + x0) * DDIM];
                    if (vx1) acc += w10 * vb[(r + x0 + 1) * DDIM];
                }
                if (vy1) {
                    int r = (y0 + 1) * w;
                    if (vx0) acc += w01 * vb[(r + x0) * DDIM];
                    if (vx1) acc += w11 * vb[(r + x0 + 1) * DDIM];
                }
            }
        }
    }
    acc *= 1.f / fmaxf(cnt, 1.f);
    g_slots[q * CDIM + h * DDIM + lane] = acc;
}

// ---------------- out projection + residual + LayerNorm ---------------------
__global__ void k_outln(const float* __restrict__ feature,
                        const float* __restrict__ W_out, const float* __restrict__ b_out,
                        const float* __restrict__ ln_g,  const float* __restrict__ ln_b,
                        float* __restrict__ out) {
    __shared__ float xs[CDIM * 16];   // first [c][k] for GEMM, then [k][c] for LN
    __shared__ float mu_s[16], rv_s[16];
    int q0 = blockIdx.x * 16, tid = threadIdx.x;

    for (int k = 0; k < 16; k++)
        xs[tid * 16 + k] = g_slots[(q0 + k) * CDIM + tid];
    __syncthreads();

    float acc[16];
    float b = b_out[tid];
#pragma unroll
    for (int k = 0; k < 16; k++) acc[k] = b;

    for (int c = 0; c < CDIM; c++) {
        float w = W_out[c * CDIM + tid];
        const float4* xc = (const float4*)&xs[c * 16];
#pragma unroll
        for (int k4 = 0; k4 < 4; k4++) {
            float4 x = xc[k4];
            acc[k4*4+0] += x.x * w; acc[k4*4+1] += x.y * w;
            acc[k4*4+2] += x.z * w; acc[k4*4+3] += x.w * w;
        }
    }
    __syncthreads();   // done reading xs
#pragma unroll
    for (int k = 0; k < 16; k++) {
        acc[k] += feature[(q0 + k) * CDIM + tid];
        xs[k * CDIM + tid] = acc[k];
    }
    __syncthreads();

    int wid = tid >> 5, lane = tid & 31;
#pragma unroll
    for (int t = 0; t < 2; t++) {
        int k = wid * 2 + t;
        float s = 0.f, ss = 0.f;
#pragma unroll
        for (int j = 0; j < 8; j++) {
            float v = xs[k * CDIM + lane + j * 32];
            s += v; ss += v * v;
        }
#pragma unroll
        for (int o = 16; o > 0; o >>= 1) {
            s  += __shfl_xor_sync(0xFFFFFFFFu, s, o);
            ss += __shfl_xor_sync(0xFFFFFFFFu, ss, o);
        }
        if (lane == 0) {
            float mu = s * (1.f / 256.f);
            mu_s[k] = mu;
            rv_s[k] = rsqrtf(ss * (1.f / 256.f) - mu * mu + 1e-5f);
        }
    }
    __syncthreads();

    float g = ln_g[tid], bb = ln_b[tid];
#pragma unroll
    for (int k = 0; k < 16; k++)
        out[(q0 + k) * CDIM + tid] = (acc[k] - mu_s[k]) * rv_s[k] * g + bb;
}

// ---------------- launch ----------------------------------------------------
extern "C" void kernel_launch(void* const* d_in, const int* in_sizes, int n_in,
                              void* d_out, int out_size) {
    const float* means      = (const float*)d_in[0];
    const float* feature    = (const float*)d_in[1];
    const float* feat0      = (const float*)d_in[2];
    const float* feat1      = (const float*)d_in[3];
    const float* feat2      = (const float*)d_in[4];
    const float* cam2ego    = (const float*)d_in[5];
    const float* intrins    = (const float*)d_in[6];
    const float* post_rots  = (const float*)d_in[7];
    const float* post_trans = (const float*)d_in[8];
    const float* W_off      = (const float*)d_in[9];
    const float* b_off      = (const float*)d_in[10];
    const float* W_attn     = (const float*)d_in[11];
    const float* b_attn     = (const float*)d_in[12];
    const float* W_val      = (const float*)d_in[13];
    const float* b_val      = (const float*)d_in[14];
    const float* W_out      = (const float*)d_in[15];
    const float* b_out      = (const float*)d_in[16];
    const float* ce         = (const float*)d_in[17];
    const float* le         = (const float*)d_in[18];
    const float* ln_g       = (const float*)d_in[19];
    const float* ln_b       = (const float*)d_in[20];
    float* out = (float*)d_out;

    k_inv<<<1, 32>>>(cam2ego);
    k_proj<<<(NC * NQ + 255) / 256, 256>>>(means, intrins, post_rots, post_trans);
    k_offattn<<<NQ / 16, 256>>>(feature, W_off, b_off, W_attn, b_attn);
    k_softmax<<<(NQ * NH + 255) / 256, 256>>>();
    dim3 gv(1386, 4);
    k_value<<<gv, 256>>>(feat0, feat1, feat2, W_val, b_val, ce, le);
    k_sampler<<<NQ, 256>>>();
    k_outln<<<NQ / 16, 256>>>(feature, W_out, b_out, ln_g, ln_b, out);
}

// round 3
// speedup vs baseline: 2.2549x; 2.2549x over previous
#include <cuda_runtime.h>
#include <cuda_fp16.h>
#include <math.h>

#define NC   6
#define NH   8
#define NL   3
#define NPT  8
#define CDIM 256
#define DDIM 32
#define NQ   6400
#define STOT 14784   // 64*176 + 32*88 + 16*44

// ---------------- scratch (device globals; no allocations allowed) ----------
__device__ float  g_inv [NC * 16];
__device__ float  g_coor[NC * NQ * 2];
__device__ float  g_mask[NC * NQ];
__device__ float  g_off [NQ * 384];
__device__ float  g_attn[NQ * 192];
__device__ float  g_slots[NQ * CDIM];
__device__ __align__(16) __half g_WhT [CDIM * CDIM];        // W_val transposed [n][k], half
__device__ __align__(16) __half g_WoaT[576 * CDIM];         // [W_off|W_attn] transposed [n][k]
__device__ float  g_embsum[NC * NL * CDIM];                 // cams+level embeds
__device__ __align__(16) __half g_value[(size_t)NC * NH * STOT * DDIM];  // 45.4 MB fp16
__device__ __align__(16) uint2  g_desc[(size_t)NQ * NH * NC * NL * NPT * 2]; // 118 MB

// ---------------- fp16 mma helper -------------------------------------------
__device__ __forceinline__ void mma16816(float* c,
    unsigned a0, unsigned a1, unsigned a2, unsigned a3,
    unsigned b0, unsigned b1) {
    asm volatile(
        "mma.sync.aligned.m16n8k16.row.col.f32.f16.f16.f32 "
        "{%0,%1,%2,%3}, {%4,%5,%6,%7}, {%8,%9}, {%0,%1,%2,%3};"
        : "+f"(c[0]), "+f"(c[1]), "+f"(c[2]), "+f"(c[3])
        : "r"(a0), "r"(a1), "r"(a2), "r"(a3), "r"(b0), "r"(b1));
}
__device__ __forceinline__ unsigned pack_h2(float a, float b) {
    __half2 h = __floats2half2_rn(a, b);
    return *(unsigned*)&h;
}

// ---------------- 4x4 inverse of cam2ego -------------------------------------
__global__ void k_inv(const float* __restrict__ cam2ego) {
    int c = threadIdx.x;
    if (c >= NC) return;
    float a[4][8];
    for (int r = 0; r < 4; r++)
        for (int j = 0; j < 4; j++) {
            a[r][j]     = cam2ego[c * 16 + r * 4 + j];
            a[r][4 + j] = (r == j) ? 1.f : 0.f;
        }
    for (int col = 0; col < 4; col++) {
        int piv = col; float mx = fabsf(a[col][col]);
        for (int r = col + 1; r < 4; r++) {
            float v = fabsf(a[r][col]);
            if (v > mx) { mx = v; piv = r; }
        }
        if (piv != col)
            for (int j = 0; j < 8; j++) { float t = a[col][j]; a[col][j] = a[piv][j]; a[piv][j] = t; }
        float inv = 1.f / a[col][col];
        for (int j = 0; j < 8; j++) a[col][j] *= inv;
        for (int r = 0; r < 4; r++) if (r != col) {
            float f = a[r][col];
            for (int j = 0; j < 8; j++) a[r][j] -= f * a[col][j];
        }
    }
    for (int r = 0; r < 4; r++)
        for (int j = 0; j < 4; j++)
            g_inv[c * 16 + r * 4 + j] = a[r][4 + j];
}

// ---------------- prep: transpose+convert weights, embed sums ----------------
__global__ void k_prep(const float* __restrict__ W_val,
                       const float* __restrict__ W_off,
                       const float* __restrict__ W_attn,
                       const float* __restrict__ ce,
                       const float* __restrict__ le) {
    int idx = blockIdx.x * 256 + threadIdx.x;
    if (idx < 65536) {
        int n = idx >> 8, k = idx & 255;
        g_WhT[n * 256 + k] = __float2half(W_val[k * 256 + n]);
        return;
    }
    idx -= 65536;
    if (idx < 147456) {
        int n = idx >> 8, k = idx & 255;
        float v = (n < 384) ? W_off[k * 384 + n] : W_attn[k * 192 + (n - 384)];
        g_WoaT[n * 256 + k] = __float2half(v);
        return;
    }
    idx -= 147456;
    if (idx < NC * NL * CDIM) {
        int cl = idx >> 8, c = idx & 255;
        g_embsum[idx] = ce[(cl / 3) * 256 + c] + le[(cl % 3) * 256 + c];
    }
}

// ---------------- projection: coor + mask per (cam, q) -----------------------
__global__ void k_proj(const float* __restrict__ means,
                       const float* __restrict__ intrins,
                       const float* __restrict__ post_rots,
                       const float* __restrict__ post_trans) {
    int idx = blockIdx.x * blockDim.x + threadIdx.x;
    if (idx >= NC * NQ) return;
    int cam = idx / NQ, q = idx % NQ;
    float mx = means[q * 3 + 0], my = means[q * 3 + 1], mz = means[q * 3 + 2];
    const float* M = g_inv + cam * 16;
    float X = M[0] * mx + M[1] * my + M[2]  * mz + M[3];
    float Y = M[4] * mx + M[5] * my + M[6]  * mz + M[7];
    float Z = M[8] * mx + M[9] * my + M[10] * mz + M[11];
    const float* I = intrins + cam * 9;
    float u  = I[0] * X + I[1] * Y + I[2] * Z;
    float v  = I[3] * X + I[4] * Y + I[5] * Z;
    float zz = I[6] * X + I[7] * Y + I[8] * Z;
    float iz = 1.f / (zz + 1e-4f);
    float m0 = u * iz, m1 = v * iz, m2 = zz;
    const float* P = post_rots + cam * 9;
    const float* T = post_trans + cam * 3;
    float px = P[0] * m0 + P[1] * m1 + P[2] * m2 + T[0];
    float py = P[3] * m0 + P[4] * m1 + P[5] * m2 + T[1];
    float pz = P[6] * m0 + P[7] * m1 + P[8] * m2 + T[2];
    float cx = px / 1408.0f;
    float cy = py / 512.0f;
    bool msk = (pz > 0.01f) && (cx > 0.f) && (cx < 1.f) && (cy > 0.f) && (cy < 1.f);
    g_coor[idx * 2 + 0] = cx;
    g_coor[idx * 2 + 1] = cy;
    g_mask[idx] = msk ? 1.f : 0.f;
}

// ---------------- offsets+attn GEMM via fp16 mma: (6400,256)@(256,576) -------
// grid (100, 3); block tile M=64 q, N=192; warp tile m64 x n24
__global__ __launch_bounds__(256) void k_offattn(
        const float* __restrict__ feature,
        const float* __restrict__ b_off, const float* __restrict__ b_attn) {
    __shared__ __half As[64 * 72];
    __shared__ __half Bs[192 * 72];

    int q0 = blockIdx.x * 64;
    int ny = blockIdx.y;           // 0..2
    int tid = threadIdx.x;
    int w = tid >> 5, lane = tid & 31;
    int g = lane >> 2, tig = lane & 3;

    float acc[4][3][4];
#pragma unroll
    for (int j = 0; j < 3; j++) {
        int col = ny * 192 + w * 24 + j * 8 + 2 * tig;
        float bv0 = (col < 384) ? b_off[col] : b_attn[col - 384];
        float bv1 = (col + 1 < 384) ? b_off[col + 1] : b_attn[col + 1 - 384];
#pragma unroll
        for (int mi = 0; mi < 4; mi++) {
            acc[mi][j][0] = bv0; acc[mi][j][1] = bv1;
            acc[mi][j][2] = bv0; acc[mi][j][3] = bv1;
        }
    }

    for (int kc = 0; kc < 4; kc++) {
        __syncthreads();
        // stage A: feature rows q0..q0+63, channels kc*64..+63
#pragma unroll
        for (int i = 0; i < 8; i++) {
            int row = w * 8 + i;
            const float2 f = *(const float2*)&feature[(q0 + row) * 256 + kc * 64 + 2 * lane];
            *(unsigned*)&As[row * 72 + 2 * lane] = pack_h2(f.x, f.y);
        }
        // stage B: WoaT rows ny*192..+191, cols kc*64..+63
#pragma unroll
        for (int t = 0; t < 12; t++) {
            int e = t * 256 + tid;
            int n = e >> 4, seg = e & 15;
            *(unsigned long long*)&Bs[n * 72 + seg * 4] =
                *(const unsigned long long*)&g_WoaT[(ny * 192 + n) * 256 + kc * 64 + seg * 4];
        }
        __syncthreads();
#pragma unroll
        for (int ks = 0; ks < 4; ks++) {
            int k2 = ks * 8;   // u32 index offset (k0/2)
            const unsigned* Ap = (const unsigned*)As;
            const unsigned* Bp = (const unsigned*)Bs;
            unsigned a[4][4];
#pragma unroll
            for (int mi = 0; mi < 4; mi++) {
                int r = mi * 16 + g;
                a[mi][0] = Ap[r * 36 + k2 + tig];
                a[mi][1] = Ap[(r + 8) * 36 + k2 + tig];
                a[mi][2] = Ap[r * 36 + k2 + 4 + tig];
                a[mi][3] = Ap[(r + 8) * 36 + k2 + 4 + tig];
            }
#pragma unroll
            for (int j = 0; j < 3; j++) {
                int n = w * 24 + j * 8 + g;
                unsigned b0 = Bp[n * 36 + k2 + tig];
                unsigned b1 = Bp[n * 36 + k2 + 4 + tig];
#pragma unroll
                for (int mi = 0; mi < 4; mi++)
                    mma16816(acc[mi][j], a[mi][0], a[mi][1], a[mi][2], a[mi][3], b0, b1);
            }
        }
    }
    // epilogue
#pragma unroll
    for (int mi = 0; mi < 4; mi++)
#pragma unroll
        for (int j = 0; j < 3; j++) {
            int col = ny * 192 + w * 24 + j * 8 + 2 * tig;
            int q = q0 + mi * 16 + g;
            float2 v0 = make_float2(acc[mi][j][0], acc[mi][j][1]);
            float2 v1 = make_float2(acc[mi][j][2], acc[mi][j][3]);
            if (col < 384) {
                *(float2*)&g_off[q * 384 + col] = v0;
                *(float2*)&g_off[(q + 8) * 384 + col] = v1;
            } else {
                *(float2*)&g_attn[q * 192 + col - 384] = v0;
                *(float2*)&g_attn[(q + 8) * 192 + col - 384] = v1;
            }
        }
}

// ---------------- softmax over 24 per (q, head) ------------------------------
__global__ void k_softmax() {
    int i = blockIdx.x * blockDim.x + threadIdx.x;
    if (i >= NQ * NH) return;
    float* p = g_attn + (i / NH) * 192 + (i % NH) * 24;
    float mx = -1e30f;
    for (int j = 0; j < 24; j++) mx = fmaxf(mx, p[j]);
    float s = 0.f;
    for (int j = 0; j < 24; j++) s += expf(p[j] - mx);
    float inv = 1.f / s;
    for (int j = 0; j < 24; j++) p[j] = expf(p[j] - mx) * inv;
}

// ---------------- tap descriptor generation ----------------------------------
// one thread per (q, h, cam, lvl, p): writes 2 row descriptors {elem_off, h2(wlo,whi)}
// layout: idx = (((q*8 + h)*6 + cam)*3 + l)*8 + p ; desc pair at idx*2
__global__ void k_desc() {
    int idx = blockIdx.x * 256 + threadIdx.x;   // 7,372,800 total
    int p   = idx & 7;
    int l   = (idx >> 3) % 3;
    int cam = (idx / 24) % 6;
    int qh  = idx / 144;                  // (q*8+h)
    int h = qh & 7, q = qh >> 3;

    const int lw[3]  = {176, 88, 44};
    const int lhh[3] = {64, 32, 16};
    const int lst[3] = {0, 11264, 14080};
    int w = lw[l], hh = lhh[l];

    float cx = g_coor[(cam * NQ + q) * 2 + 0];
    float cy = g_coor[(cam * NQ + q) * 2 + 1];
    float m  = g_mask[cam * NQ + q];
    int oi = ((h * 3 + l) * 8 + p) * 2;
    float x = cx * (float)w  - 0.5f + g_off[q * 384 + oi];
    float y = cy * (float)hh - 0.5f + g_off[q * 384 + oi + 1];
    float am = g_attn[q * 192 + h * 24 + l * 8 + p] * m;

    float xf = floorf(x), yf = floorf(y);
    float tx = x - xf, ty = y - yf;
    int x0 = (int)xf, y0 = (int)yf;
    float wx0 = ((x0 >= 0) && (x0 < w)) ? (1.f - tx) : 0.f;
    float wx1 = ((x0 + 1 >= 0) && (x0 + 1 < w)) ? tx : 0.f;
    int xb = min(max(x0, 0), w - 2);
    float wlo = (xb == x0) ? wx0 : ((xb == x0 + 1) ? wx1 : 0.f);
    float whi = (xb == x0) ? wx1 : ((xb == x0 - 1) ? wx0 : 0.f);

    size_t dbase = (size_t)idx * 2;
#pragma unroll
    for (int rv = 0; rv < 2; rv++) {
        int r = y0 + rv;
        float wy = ((r >= 0) && (r < hh)) ? (rv ? ty : (1.f - ty)) : 0.f;
        int rr = min(max(r, 0), hh - 1);
        unsigned off = (unsigned)(((cam * 8 + h) * STOT + lst[l] + rr * w + xb) * 32);
        uint2 d;
        d.x = off;
        __half2 wp = __floats2half2_rn(am * wy * wlo, am * wy * whi);
        d.y = *(unsigned*)&wp;
        g_desc[dbase + rv] = d;
    }
}

// ---------------- value build + GEMM via fp16 mma ----------------------------
// grid 1386; block tile M=64 pixels, N=256 channels; warp tile m64 x n32 (one head)
__global__ __launch_bounds__(256) void k_value(
        const float* __restrict__ feat0,
        const float* __restrict__ feat1,
        const float* __restrict__ feat2,
        const float* __restrict__ b_val) {
    __shared__ __half As[64 * 72];
    __shared__ __half Bs[256 * 72];

    int bx = blockIdx.x;
    int cam = bx / 231, rb = bx % 231;
    int lvl, hw, pix0; const float* fb;
    if (rb < 176)      { lvl = 0; hw = 11264; pix0 = rb * 64;          fb = feat0; }
    else if (rb < 220) { lvl = 1; hw = 2816;  pix0 = (rb - 176) * 64;  fb = feat1; }
    else               { lvl = 2; hw = 704;   pix0 = (rb - 220) * 64;  fb = feat2; }
    fb += (size_t)cam * CDIM * hw;
    int m0 = rb * 64;
    const float* emb = g_embsum + (cam * 3 + lvl) * 256;

    int tid = threadIdx.x;
    int w = tid >> 5, lane = tid & 31;
    int g = lane >> 2, tig = lane & 3;

    float acc[4][4][4];
#pragma unroll
    for (int j = 0; j < 4; j++) {
        int d = j * 8 + 2 * tig;
        float bv0 = b_val[w * 32 + d], bv1 = b_val[w * 32 + d + 1];
#pragma unroll
        for (int mi = 0; mi < 4; mi++) {
            acc[mi][j][0] = bv0; acc[mi][j][1] = bv1;
            acc[mi][j][2] = bv0; acc[mi][j][3] = bv1;
        }
    }

    for (int kc = 0; kc < 4; kc++) {
        __syncthreads();
        // stage A: 64 pixels x 64 channels (+embeds), converted to half
#pragma unroll
        for (int i = 0; i < 4; i++) {
            int cp = w * 4 + i;
            int c = kc * 64 + cp * 2;
            float e0 = emb[c], e1 = emb[c + 1];
#pragma unroll
            for (int j = 0; j < 2; j++) {
                int pix = lane + 32 * j;
                float f0 = fb[(size_t)c * hw + pix0 + pix] + e0;
                float f1 = fb[(size_t)(c + 1) * hw + pix0 + pix] + e1;
                *(unsigned*)&As[pix * 72 + cp * 2] = pack_h2(f0, f1);
            }
        }
        // stage B: WhT rows 0..255, cols kc*64..+63
#pragma unroll
        for (int t = 0; t < 16; t++) {
            int e = t * 256 + tid;
            int n = e >> 4, seg = e & 15;
            *(unsigned long long*)&Bs[n * 72 + seg * 4] =
                *(const unsigned long long*)&g_WhT[n * 256 + kc * 64 + seg * 4];
        }
        __syncthreads();
#pragma unroll
        for (int ks = 0; ks < 4; ks++) {
            int k2 = ks * 8;
            const unsigned* Ap = (const unsigned*)As;
            const unsigned* Bp = (const unsigned*)Bs;
            unsigned a[4][4];
#pragma unroll
            for (int mi = 0; mi < 4; mi++) {
                int r = mi * 16 + g;
                a[mi][0] = Ap[r * 36 + k2 + tig];
                a[mi][1] = Ap[(r + 8) * 36 + k2 + tig];
                a[mi][2] = Ap[r * 36 + k2 + 4 + tig];
                a[mi][3] = Ap[(r + 8) * 36 + k2 + 4 + tig];
            }
#pragma unroll
            for (int j = 0; j < 4; j++) {
                int n = w * 32 + j * 8 + g;
                unsigned b0 = Bp[n * 36 + k2 + tig];
                unsigned b1 = Bp[n * 36 + k2 + 4 + tig];
#pragma unroll
                for (int mi = 0; mi < 4; mi++)
                    mma16816(acc[mi][j], a[mi][0], a[mi][1], a[mi][2], a[mi][3], b0, b1);
            }
        }
    }
    // epilogue: half2 stores into g_value[cam][head=w][s][d]
    size_t vbase = ((size_t)(cam * 8 + w) * STOT) * 32;
#pragma unroll
    for (int mi = 0; mi < 4; mi++)
#pragma unroll
        for (int j = 0; j < 4; j++) {
            int d = j * 8 + 2 * tig;
            int s = m0 + mi * 16 + g;
            *(unsigned*)&g_value[vbase + (size_t)s * 32 + d] = pack_h2(acc[mi][j][0], acc[mi][j][1]);
            *(unsigned*)&g_value[vbase + (size_t)(s + 8) * 32 + d] = pack_h2(acc[mi][j][2], acc[mi][j][3]);
        }
}

// ---------------- gather: block per query, warp per head ---------------------
__global__ __launch_bounds__(256) void k_gather() {
    int q = blockIdx.x, tid = threadIdx.x;
    int h = tid >> 5, lane = tid & 31;

    const uint2* dp = g_desc + (size_t)(q * 8 + h) * 288;
    float ax = 0.f, ay = 0.f;
#pragma unroll 4
    for (int i = 0; i < 288; i++) {
        uint2 d = __ldg(dp + i);
        __half2 wh = *(__half2*)&d.y;
        float2 wf = __half22float2(wh);
        float wgt = (lane < 16) ? wf.x : wf.y;
        __half2 v = *(const __half2*)(g_value + d.x + 2 * lane);
        float2 vf = __half22float2(v);
        ax += wgt * vf.x;
        ay += wgt * vf.y;
    }
    ax += __shfl_xor_sync(0xFFFFFFFFu, ax, 16);
    ay += __shfl_xor_sync(0xFFFFFFFFu, ay, 16);

    float cnt = 0.f;
#pragma unroll
    for (int c = 0; c < 6; c++) cnt += g_mask[c * NQ + q];
    float inv = 1.f / fmaxf(cnt, 1.f);

    if (lane < 16) {
        float2 o = make_float2(ax * inv, ay * inv);
        *(float2*)&g_slots[q * 256 + h * 32 + 2 * lane] = o;
    }
}

// ---------------- out projection + residual + LayerNorm ----------------------
__global__ void k_outln(const float* __restrict__ feature,
                        const float* __restrict__ W_out, const float* __restrict__ b_out,
                        const float* __restrict__ ln_g,  const float* __restrict__ ln_b,
                        float* __restrict__ out) {
    __shared__ float xs[CDIM * 16];
    __shared__ float mu_s[16], rv_s[16];
    int q0 = blockIdx.x * 16, tid = threadIdx.x;

    for (int k = 0; k < 16; k++)
        xs[tid * 16 + k] = g_slots[(q0 + k) * CDIM + tid];
    __syncthreads();

    float acc[16];
    float b = b_out[tid];
#pragma unroll
    for (int k = 0; k < 16; k++) acc[k] = b;

    for (int c = 0; c < CDIM; c++) {
        float w = W_out[c * CDIM + tid];
        const float4* xc = (const float4*)&xs[c * 16];
#pragma unroll
        for (int k4 = 0; k4 < 4; k4++) {
            float4 x = xc[k4];
            acc[k4*4+0] += x.x * w; acc[k4*4+1] += x.y * w;
            acc[k4*4+2] += x.z * w; acc[k4*4+3] += x.w * w;
        }
    }
    __syncthreads();
#pragma unroll
    for (int k = 0; k < 16; k++) {
        acc[k] += feature[(q0 + k) * CDIM + tid];
        xs[k * CDIM + tid] = acc[k];
    }
    __syncthreads();

    int wid = tid >> 5, lane = tid & 31;
#pragma unroll
    for (int t = 0; t < 2; t++) {
        int k = wid * 2 + t;
        float s = 0.f, ss = 0.f;
#pragma unroll
        for (int j = 0; j < 8; j++) {
            float v = xs[k * CDIM + lane + j * 32];
            s += v; ss += v * v;
        }
#pragma unroll
        for (int o = 16; o > 0; o >>= 1) {
            s  += __shfl_xor_sync(0xFFFFFFFFu, s, o);
            ss += __shfl_xor_sync(0xFFFFFFFFu, ss, o);
        }
        if (lane == 0) {
            float mu = s * (1.f / 256.f);
            mu_s[k] = mu;
            rv_s[k] = rsqrtf(ss * (1.f / 256.f) - mu * mu + 1e-5f);
        }
    }
    __syncthreads();

    float g = ln_g[tid], bb = ln_b[tid];
#pragma unroll
    for (int k = 0; k < 16; k++)
        out[(q0 + k) * CDIM + tid] = (acc[k] - mu_s[k]) * rv_s[k] * g + bb;
}

// ---------------- launch ------------------------------------------------------
extern "C" void kernel_launch(void* const* d_in, const int* in_sizes, int n_in,
                              void* d_out, int out_size) {
    const float* means      = (const float*)d_in[0];
    const float* feature    = (const float*)d_in[1];
    const float* feat0      = (const float*)d_in[2];
    const float* feat1      = (const float*)d_in[3];
    const float* feat2      = (const float*)d_in[4];
    const float* cam2ego    = (const float*)d_in[5];
    const float* intrins    = (const float*)d_in[6];
    const float* post_rots  = (const float*)d_in[7];
    const float* post_trans = (const float*)d_in[8];
    const float* W_off      = (const float*)d_in[9];
    const float* b_off      = (const float*)d_in[10];
    const float* W_attn     = (const float*)d_in[11];
    const float* b_attn     = (const float*)d_in[12];
    const float* W_val      = (const float*)d_in[13];
    const float* b_val      = (const float*)d_in[14];
    const float* W_out      = (const float*)d_in[15];
    const float* b_out      = (const float*)d_in[16];
    const float* ce         = (const float*)d_in[17];
    const float* le         = (const float*)d_in[18];
    const float* ln_g       = (const float*)d_in[19];
    const float* ln_b       = (const float*)d_in[20];
    float* out = (float*)d_out;

    k_inv<<<1, 32>>>(cam2ego);
    k_prep<<<(65536 + 147456 + NC * NL * CDIM + 255) / 256, 256>>>(W_val, W_off, W_attn, ce, le);
    k_proj<<<(NC * NQ + 255) / 256, 256>>>(means, intrins, post_rots, post_trans);
    k_offattn<<<dim3(100, 3), 256>>>(feature, b_off, b_attn);
    k_softmax<<<(NQ * NH + 255) / 256, 256>>>();
    k_desc<<<28800, 256>>>();
    k_value<<<1386, 256>>>(feat0, feat1, feat2, b_val);
    k_gather<<<NQ, 256>>>();
    k_outln<<<NQ / 16, 256>>>(feature, W_out, b_out, ln_g, ln_b, out);
}

// round 4
// speedup vs baseline: 3.1014x; 1.3754x over previous
#include <cuda_runtime.h>
#include <cuda_fp16.h>
#include <math.h>

#define NC   6
#define NH   8
#define NL   3
#define NPT  8
#define CDIM 256
#define DDIM 32
#define NQ   6400
#define STOT 14784   // 64*176 + 32*88 + 16*44

// ---------------- scratch (device globals; no allocations allowed) ----------
__device__ float  g_inv [NC * 16];
__device__ float  g_coor[NC * NQ * 2];
__device__ float  g_mask[NC * NQ];
__device__ float  g_off [NQ * 384];
__device__ float  g_attn[NQ * 192];
__device__ float  g_slots[NQ * CDIM];
__device__ __align__(16) __half g_WhT [CDIM * CDIM];        // W_val transposed [n][k], half
__device__ __align__(16) __half g_WoaT[576 * CDIM];         // [W_off|W_attn] transposed [n][k]
__device__ float  g_embsum[NC * NL * CDIM];                 // cams+level embeds
__device__ __align__(16) __half g_value[(size_t)NC * NH * STOT * DDIM];  // 45.4 MB fp16

// ---------------- fp16 mma helper -------------------------------------------
__device__ __forceinline__ void mma16816(float* c,
    unsigned a0, unsigned a1, unsigned a2, unsigned a3,
    unsigned b0, unsigned b1) {
    asm volatile(
        "mma.sync.aligned.m16n8k16.row.col.f32.f16.f16.f32 "
        "{%0,%1,%2,%3}, {%4,%5,%6,%7}, {%8,%9}, {%0,%1,%2,%3};"
        : "+f"(c[0]), "+f"(c[1]), "+f"(c[2]), "+f"(c[3])
        : "r"(a0), "r"(a1), "r"(a2), "r"(a3), "r"(b0), "r"(b1));
}
__device__ __forceinline__ unsigned pack_h2(float a, float b) {
    __half2 h = __floats2half2_rn(a, b);
    return *(unsigned*)&h;
}

// ---------------- 4x4 inverse of cam2ego -------------------------------------
__global__ void k_inv(const float* __restrict__ cam2ego) {
    int c = threadIdx.x;
    if (c >= NC) return;
    float a[4][8];
    for (int r = 0; r < 4; r++)
        for (int j = 0; j < 4; j++) {
            a[r][j]     = cam2ego[c * 16 + r * 4 + j];
            a[r][4 + j] = (r == j) ? 1.f : 0.f;
        }
    for (int col = 0; col < 4; col++) {
        int piv = col; float mx = fabsf(a[col][col]);
        for (int r = col + 1; r < 4; r++) {
            float v = fabsf(a[r][col]);
            if (v > mx) { mx = v; piv = r; }
        }
        if (piv != col)
            for (int j = 0; j < 8; j++) { float t = a[col][j]; a[col][j] = a[piv][j]; a[piv][j] = t; }
        float inv = 1.f / a[col][col];
        for (int j = 0; j < 8; j++) a[col][j] *= inv;
        for (int r = 0; r < 4; r++) if (r != col) {
            float f = a[r][col];
            for (int j = 0; j < 8; j++) a[r][j] -= f * a[col][j];
        }
    }
    for (int r = 0; r < 4; r++)
        for (int j = 0; j < 4; j++)
            g_inv[c * 16 + r * 4 + j] = a[r][4 + j];
}

// ---------------- prep: transpose+convert weights, embed sums ----------------
__global__ void k_prep(const float* __restrict__ W_val,
                       const float* __restrict__ W_off,
                       const float* __restrict__ W_attn,
                       const float* __restrict__ ce,
                       const float* __restrict__ le) {
    int idx = blockIdx.x * 256 + threadIdx.x;
    if (idx < 65536) {
        int n = idx >> 8, k = idx & 255;
        g_WhT[n * 256 + k] = __float2half(W_val[k * 256 + n]);
        return;
    }
    idx -= 65536;
    if (idx < 147456) {
        int n = idx >> 8, k = idx & 255;
        float v = (n < 384) ? W_off[k * 384 + n] : W_attn[k * 192 + (n - 384)];
        g_WoaT[n * 256 + k] = __float2half(v);
        return;
    }
    idx -= 147456;
    if (idx < NC * NL * CDIM) {
        int cl = idx >> 8, c = idx & 255;
        g_embsum[idx] = ce[(cl / 3) * 256 + c] + le[(cl % 3) * 256 + c];
    }
}

// ---------------- projection: coor + mask per (cam, q) -----------------------
__global__ void k_proj(const float* __restrict__ means,
                       const float* __restrict__ intrins,
                       const float* __restrict__ post_rots,
                       const float* __restrict__ post_trans) {
    int idx = blockIdx.x * blockDim.x + threadIdx.x;
    if (idx >= NC * NQ) return;
    int cam = idx / NQ, q = idx % NQ;
    float mx = means[q * 3 + 0], my = means[q * 3 + 1], mz = means[q * 3 + 2];
    const float* M = g_inv + cam * 16;
    float X = M[0] * mx + M[1] * my + M[2]  * mz + M[3];
    float Y = M[4] * mx + M[5] * my + M[6]  * mz + M[7];
    float Z = M[8] * mx + M[9] * my + M[10] * mz + M[11];
    const float* I = intrins + cam * 9;
    float u  = I[0] * X + I[1] * Y + I[2] * Z;
    float v  = I[3] * X + I[4] * Y + I[5] * Z;
    float zz = I[6] * X + I[7] * Y + I[8] * Z;
    float iz = 1.f / (zz + 1e-4f);
    float m0 = u * iz, m1 = v * iz, m2 = zz;
    const float* P = post_rots + cam * 9;
    const float* T = post_trans + cam * 3;
    float px = P[0] * m0 + P[1] * m1 + P[2] * m2 + T[0];
    float py = P[3] * m0 + P[4] * m1 + P[5] * m2 + T[1];
    float pz = P[6] * m0 + P[7] * m1 + P[8] * m2 + T[2];
    float cx = px / 1408.0f;
    float cy = py / 512.0f;
    bool msk = (pz > 0.01f) && (cx > 0.f) && (cx < 1.f) && (cy > 0.f) && (cy < 1.f);
    g_coor[idx * 2 + 0] = cx;
    g_coor[idx * 2 + 1] = cy;
    g_mask[idx] = msk ? 1.f : 0.f;
}

// ---------------- offsets+attn GEMM via fp16 mma, softmax fused --------------
// grid (100, 3); block tile M=64 q, N=192; warp tile m64 x n24
// ny==2 block holds ALL attention logits (cols 384..575); each head's 24
// logits for a given query row live within one quad -> in-register softmax.
__global__ __launch_bounds__(256) void k_offattn(
        const float* __restrict__ feature,
        const float* __restrict__ b_off, const float* __restrict__ b_attn) {
    __shared__ __half As[64 * 72];
    __shared__ __half Bs[192 * 72];

    int q0 = blockIdx.x * 64;
    int ny = blockIdx.y;           // 0..2
    int tid = threadIdx.x;
    int w = tid >> 5, lane = tid & 31;
    int g = lane >> 2, tig = lane & 3;

    float acc[4][3][4];
#pragma unroll
    for (int j = 0; j < 3; j++) {
        int col = ny * 192 + w * 24 + j * 8 + 2 * tig;
        float bv0 = (col < 384) ? b_off[col] : b_attn[col - 384];
        float bv1 = (col + 1 < 384) ? b_off[col + 1] : b_attn[col + 1 - 384];
#pragma unroll
        for (int mi = 0; mi < 4; mi++) {
            acc[mi][j][0] = bv0; acc[mi][j][1] = bv1;
            acc[mi][j][2] = bv0; acc[mi][j][3] = bv1;
        }
    }

    for (int kc = 0; kc < 4; kc++) {
        __syncthreads();
#pragma unroll
        for (int i = 0; i < 8; i++) {
            int row = w * 8 + i;
            const float2 f = *(const float2*)&feature[(q0 + row) * 256 + kc * 64 + 2 * lane];
            *(unsigned*)&As[row * 72 + 2 * lane] = pack_h2(f.x, f.y);
        }
#pragma unroll
        for (int t = 0; t < 12; t++) {
            int e = t * 256 + tid;
            int n = e >> 4, seg = e & 15;
            *(unsigned long long*)&Bs[n * 72 + seg * 4] =
                *(const unsigned long long*)&g_WoaT[(ny * 192 + n) * 256 + kc * 64 + seg * 4];
        }
        __syncthreads();
#pragma unroll
        for (int ks = 0; ks < 4; ks++) {
            int k2 = ks * 8;
            const unsigned* Ap = (const unsigned*)As;
            const unsigned* Bp = (const unsigned*)Bs;
            unsigned a[4][4];
#pragma unroll
            for (int mi = 0; mi < 4; mi++) {
                int r = mi * 16 + g;
                a[mi][0] = Ap[r * 36 + k2 + tig];
                a[mi][1] = Ap[(r + 8) * 36 + k2 + tig];
                a[mi][2] = Ap[r * 36 + k2 + 4 + tig];
                a[mi][3] = Ap[(r + 8) * 36 + k2 + 4 + tig];
            }
#pragma unroll
            for (int j = 0; j < 3; j++) {
                int n = w * 24 + j * 8 + g;
                unsigned b0 = Bp[n * 36 + k2 + tig];
                unsigned b1 = Bp[n * 36 + k2 + 4 + tig];
#pragma unroll
                for (int mi = 0; mi < 4; mi++)
                    mma16816(acc[mi][j], a[mi][0], a[mi][1], a[mi][2], a[mi][3], b0, b1);
            }
        }
    }

    if (ny < 2) {
        // offsets only
#pragma unroll
        for (int mi = 0; mi < 4; mi++)
#pragma unroll
            for (int j = 0; j < 3; j++) {
                int col = ny * 192 + w * 24 + j * 8 + 2 * tig;
                int q = q0 + mi * 16 + g;
                *(float2*)&g_off[q * 384 + col] = make_float2(acc[mi][j][0], acc[mi][j][1]);
                *(float2*)&g_off[(q + 8) * 384 + col] = make_float2(acc[mi][j][2], acc[mi][j][3]);
            }
    } else {
        // attention logits: softmax over 24 (j x 2 x quad) per row, then store
        const unsigned FULL = 0xFFFFFFFFu;
#pragma unroll
        for (int mi = 0; mi < 4; mi++) {
            float mA = -1e30f, mB = -1e30f;
#pragma unroll
            for (int j = 0; j < 3; j++) {
                mA = fmaxf(mA, fmaxf(acc[mi][j][0], acc[mi][j][1]));
                mB = fmaxf(mB, fmaxf(acc[mi][j][2], acc[mi][j][3]));
            }
            mA = fmaxf(mA, __shfl_xor_sync(FULL, mA, 1));
            mA = fmaxf(mA, __shfl_xor_sync(FULL, mA, 2));
            mB = fmaxf(mB, __shfl_xor_sync(FULL, mB, 1));
            mB = fmaxf(mB, __shfl_xor_sync(FULL, mB, 2));
            float sA = 0.f, sB = 0.f;
#pragma unroll
            for (int j = 0; j < 3; j++) {
                acc[mi][j][0] = __expf(acc[mi][j][0] - mA);
                acc[mi][j][1] = __expf(acc[mi][j][1] - mA);
                acc[mi][j][2] = __expf(acc[mi][j][2] - mB);
                acc[mi][j][3] = __expf(acc[mi][j][3] - mB);
                sA += acc[mi][j][0] + acc[mi][j][1];
                sB += acc[mi][j][2] + acc[mi][j][3];
            }
            sA += __shfl_xor_sync(FULL, sA, 1);
            sA += __shfl_xor_sync(FULL, sA, 2);
            sB += __shfl_xor_sync(FULL, sB, 1);
            sB += __shfl_xor_sync(FULL, sB, 2);
            float iA = 1.f / sA, iB = 1.f / sB;
#pragma unroll
            for (int j = 0; j < 3; j++) {
                int col = w * 24 + j * 8 + 2 * tig;
                int q = q0 + mi * 16 + g;
                *(float2*)&g_attn[q * 192 + col] =
                    make_float2(acc[mi][j][0] * iA, acc[mi][j][1] * iA);
                *(float2*)&g_attn[(q + 8) * 192 + col] =
                    make_float2(acc[mi][j][2] * iB, acc[mi][j][3] * iB);
            }
        }
    }
}

// ---------------- value build + GEMM via fp16 mma ----------------------------
__global__ __launch_bounds__(256) void k_value(
        const float* __restrict__ feat0,
        const float* __restrict__ feat1,
        const float* __restrict__ feat2,
        const float* __restrict__ b_val) {
    __shared__ __half As[64 * 72];
    __shared__ __half Bs[256 * 72];

    int bx = blockIdx.x;
    int cam = bx / 231, rb = bx % 231;
    int lvl, hw, pix0; const float* fb;
    if (rb < 176)      { lvl = 0; hw = 11264; pix0 = rb * 64;          fb = feat0; }
    else if (rb < 220) { lvl = 1; hw = 2816;  pix0 = (rb - 176) * 64;  fb = feat1; }
    else               { lvl = 2; hw = 704;   pix0 = (rb - 220) * 64;  fb = feat2; }
    fb += (size_t)cam * CDIM * hw;
    int m0 = rb * 64;
    const float* emb = g_embsum + (cam * 3 + lvl) * 256;

    int tid = threadIdx.x;
    int w = tid >> 5, lane = tid & 31;
    int g = lane >> 2, tig = lane & 3;

    float acc[4][4][4];
#pragma unroll
    for (int j = 0; j < 4; j++) {
        int d = j * 8 + 2 * tig;
        float bv0 = b_val[w * 32 + d], bv1 = b_val[w * 32 + d + 1];
#pragma unroll
        for (int mi = 0; mi < 4; mi++) {
            acc[mi][j][0] = bv0; acc[mi][j][1] = bv1;
            acc[mi][j][2] = bv0; acc[mi][j][3] = bv1;
        }
    }

    for (int kc = 0; kc < 4; kc++) {
        __syncthreads();
#pragma unroll
        for (int i = 0; i < 4; i++) {
            int cp = w * 4 + i;
            int c = kc * 64 + cp * 2;
            float e0 = emb[c], e1 = emb[c + 1];
#pragma unroll
            for (int j = 0; j < 2; j++) {
                int pix = lane + 32 * j;
                float f0 = fb[(size_t)c * hw + pix0 + pix] + e0;
                float f1 = fb[(size_t)(c + 1) * hw + pix0 + pix] + e1;
                *(unsigned*)&As[pix * 72 + cp * 2] = pack_h2(f0, f1);
            }
        }
#pragma unroll
        for (int t = 0; t < 16; t++) {
            int e = t * 256 + tid;
            int n = e >> 4, seg = e & 15;
            *(unsigned long long*)&Bs[n * 72 + seg * 4] =
                *(const unsigned long long*)&g_WhT[n * 256 + kc * 64 + seg * 4];
        }
        __syncthreads();
#pragma unroll
        for (int ks = 0; ks < 4; ks++) {
            int k2 = ks * 8;
            const unsigned* Ap = (const unsigned*)As;
            const unsigned* Bp = (const unsigned*)Bs;
            unsigned a[4][4];
#pragma unroll
            for (int mi = 0; mi < 4; mi++) {
                int r = mi * 16 + g;
                a[mi][0] = Ap[r * 36 + k2 + tig];
                a[mi][1] = Ap[(r + 8) * 36 + k2 + tig];
                a[mi][2] = Ap[r * 36 + k2 + 4 + tig];
                a[mi][3] = Ap[(r + 8) * 36 + k2 + 4 + tig];
            }
#pragma unroll
            for (int j = 0; j < 4; j++) {
                int n = w * 32 + j * 8 + g;
                unsigned b0 = Bp[n * 36 + k2 + tig];
                unsigned b1 = Bp[n * 36 + k2 + 4 + tig];
#pragma unroll
                for (int mi = 0; mi < 4; mi++)
                    mma16816(acc[mi][j], a[mi][0], a[mi][1], a[mi][2], a[mi][3], b0, b1);
            }
        }
    }
    size_t vbase = ((size_t)(cam * 8 + w) * STOT) * 32;
#pragma unroll
    for (int mi = 0; mi < 4; mi++)
#pragma unroll
        for (int j = 0; j < 4; j++) {
            int d = j * 8 + 2 * tig;
            int s = m0 + mi * 16 + g;
            *(unsigned*)&g_value[vbase + (size_t)s * 32 + d] = pack_h2(acc[mi][j][0], acc[mi][j][1]);
            *(unsigned*)&g_value[vbase + (size_t)(s + 8) * 32 + d] = pack_h2(acc[mi][j][2], acc[mi][j][3]);
        }
}

// ---------------- fused desc+gather: block per query, warp per head ----------
// Phase 1: 256 threads compute 1152 tap descriptors into smem (uint4 each:
//          {row0_off, row0_w(h2 lo/hi), row1_off, row1_w}); 1/cnt folded in.
// Phase 2: warp h walks its 144 descs; lane bits: b4=row, b3=x-col, b0..2=ch/4.
__global__ __launch_bounds__(256) void k_gather() {
    __shared__ __align__(16) uint4 s_desc[1152];
    __shared__ float s_off[384];
    __shared__ float s_attn[192];
    __shared__ float s_coor[12];
    __shared__ float s_mask[6];

    int q = blockIdx.x, tid = threadIdx.x;

    s_off[tid] = g_off[q * 384 + tid];
    if (tid < 128) s_off[256 + tid] = g_off[q * 384 + 256 + tid];
    if (tid < 192) s_attn[tid] = g_attn[q * 192 + tid];
    if (tid < 12)  s_coor[tid] = g_coor[((tid >> 1) * NQ + q) * 2 + (tid & 1)];
    if (tid < 6)   s_mask[tid] = g_mask[tid * NQ + q];
    __syncthreads();

    float cnt = s_mask[0] + s_mask[1] + s_mask[2] + s_mask[3] + s_mask[4] + s_mask[5];
    float inv = 1.f / fmaxf(cnt, 1.f);

    const int lw[3]  = {176, 88, 44};
    const int lhh[3] = {64, 32, 16};
    const int lst[3] = {0, 11264, 14080};

    for (int t = tid; t < 1152; t += 256) {
        int h = t / 144, i = t % 144;
        int cam = i / 24, l = (i >> 3) % 3, p = i & 7;
        int w = lw[l], hh = lhh[l];
        float cx = s_coor[cam * 2], cy = s_coor[cam * 2 + 1];
        int oi = ((h * 3 + l) * 8 + p) * 2;
        float x = cx * (float)w  - 0.5f + s_off[oi];
        float y = cy * (float)hh - 0.5f + s_off[oi + 1];
        float am = s_attn[h * 24 + l * 8 + p] * s_mask[cam] * inv;

        float xf = floorf(x), yf = floorf(y);
        float tx = x - xf, ty = y - yf;
        int x0 = (int)xf, y0 = (int)yf;
        float wx0 = ((x0 >= 0) && (x0 < w)) ? (1.f - tx) : 0.f;
        float wx1 = ((x0 + 1 >= 0) && (x0 + 1 < w)) ? tx : 0.f;
        int xb = min(max(x0, 0), w - 2);
        float wlo = (xb == x0) ? wx0 : ((xb == x0 + 1) ? wx1 : 0.f);
        float whi = (xb == x0) ? wx1 : ((xb == x0 - 1) ? wx0 : 0.f);

        unsigned base = (unsigned)((cam * 8 + h) * STOT + lst[l] + xb);
        uint4 d;
        {
            int r = y0;
            float wy = ((r >= 0) && (r < hh)) ? (1.f - ty) : 0.f;
            int rr = min(max(r, 0), hh - 1);
            d.x = (base + (unsigned)(rr * w)) * 32u;
            d.y = pack_h2(am * wy * wlo, am * wy * whi);
        }
        {
            int r = y0 + 1;
            float wy = ((r >= 0) && (r < hh)) ? ty : 0.f;
            int rr = min(max(r, 0), hh - 1);
            d.z = (base + (unsigned)(rr * w)) * 32u;
            d.w = pack_h2(am * wy * wlo, am * wy * whi);
        }
        s_desc[t] = d;
    }
    __syncthreads();

    int h = tid >> 5, lane = tid & 31;
    int halfr = lane >> 4, col = (lane >> 3) & 1, lc = lane & 7;
    int laneoff = col * 32 + lc * 4;
    const uint4* dp = s_desc + h * 144;

    float a0 = 0.f, a1 = 0.f, a2 = 0.f, a3 = 0.f;
#pragma unroll 4
    for (int i = 0; i < 144; i++) {
        uint4 d = dp[i];
        unsigned off = halfr ? d.z : d.x;
        unsigned wr  = halfr ? d.w : d.y;
        float2 wf = __half22float2(*(__half2*)&wr);
        float wgt = col ? wf.y : wf.x;
        uint2 v = *(const uint2*)(g_value + off + laneoff);
        float2 f01 = __half22float2(*(__half2*)&v.x);
        float2 f23 = __half22float2(*(__half2*)&v.y);
        a0 += wgt * f01.x; a1 += wgt * f01.y;
        a2 += wgt * f23.x; a3 += wgt * f23.y;
    }
    const unsigned FULL = 0xFFFFFFFFu;
    a0 += __shfl_xor_sync(FULL, a0, 8);
    a1 += __shfl_xor_sync(FULL, a1, 8);
    a2 += __shfl_xor_sync(FULL, a2, 8);
    a3 += __shfl_xor_sync(FULL, a3, 8);
    a0 += __shfl_xor_sync(FULL, a0, 16);
    a1 += __shfl_xor_sync(FULL, a1, 16);
    a2 += __shfl_xor_sync(FULL, a2, 16);
    a3 += __shfl_xor_sync(FULL, a3, 16);

    if (lane < 8)
        *(float4*)&g_slots[q * 256 + h * 32 + lc * 4] = make_float4(a0, a1, a2, a3);
}

// ---------------- out projection + residual + LayerNorm ----------------------
__global__ void k_outln(const float* __restrict__ feature,
                        const float* __restrict__ W_out, const float* __restrict__ b_out,
                        const float* __restrict__ ln_g,  const float* __restrict__ ln_b,
                        float* __restrict__ out) {
    __shared__ float xs[CDIM * 16];
    __shared__ float mu_s[16], rv_s[16];
    int q0 = blockIdx.x * 16, tid = threadIdx.x;

    for (int k = 0; k < 16; k++)
        xs[tid * 16 + k] = g_slots[(q0 + k) * CDIM + tid];
    __syncthreads();

    float acc[16];
    float b = b_out[tid];
#pragma unroll
    for (int k = 0; k < 16; k++) acc[k] = b;

    for (int c = 0; c < CDIM; c++) {
        float w = W_out[c * CDIM + tid];
        const float4* xc = (const float4*)&xs[c * 16];
#pragma unroll
        for (int k4 = 0; k4 < 4; k4++) {
            float4 x = xc[k4];
            acc[k4*4+0] += x.x * w; acc[k4*4+1] += x.y * w;
            acc[k4*4+2] += x.z * w; acc[k4*4+3] += x.w * w;
        }
    }
    __syncthreads();
#pragma unroll
    for (int k = 0; k < 16; k++) {
        acc[k] += feature[(q0 + k) * CDIM + tid];
        xs[k * CDIM + tid] = acc[k];
    }
    __syncthreads();

    int wid = tid >> 5, lane = tid & 31;
#pragma unroll
    for (int t = 0; t < 2; t++) {
        int k = wid * 2 + t;
        float s = 0.f, ss = 0.f;
#pragma unroll
        for (int j = 0; j < 8; j++) {
            float v = xs[k * CDIM + lane + j * 32];
            s += v; ss += v * v;
        }
#pragma unroll
        for (int o = 16; o > 0; o >>= 1) {
            s  += __shfl_xor_sync(0xFFFFFFFFu, s, o);
            ss += __shfl_xor_sync(0xFFFFFFFFu, ss, o);
        }
        if (lane == 0) {
            float mu = s * (1.f / 256.f);
            mu_s[k] = mu;
            rv_s[k] = rsqrtf(ss * (1.f / 256.f) - mu * mu + 1e-5f);
        }
    }
    __syncthreads();

    float g = ln_g[tid], bb = ln_b[tid];
#pragma unroll
    for (int k = 0; k < 16; k++)
        out[(q0 + k) * CDIM + tid] = (acc[k] - mu_s[k]) * rv_s[k] * g + bb;
}

// ---------------- launch ------------------------------------------------------
extern "C" void kernel_launch(void* const* d_in, const int* in_sizes, int n_in,
                              void* d_out, int out_size) {
    const float* means      = (const float*)d_in[0];
    const float* feature    = (const float*)d_in[1];
    const float* feat0      = (const float*)d_in[2];
    const float* feat1      = (const float*)d_in[3];
    const float* feat2      = (const float*)d_in[4];
    const float* cam2ego    = (const float*)d_in[5];
    const float* intrins    = (const float*)d_in[6];
    const float* post_rots  = (const float*)d_in[7];
    const float* post_trans = (const float*)d_in[8];
    const float* W_off      = (const float*)d_in[9];
    const float* b_off      = (const float*)d_in[10];
    const float* W_attn     = (const float*)d_in[11];
    const float* b_attn     = (const float*)d_in[12];
    const float* W_val      = (const float*)d_in[13];
    const float* b_val      = (const float*)d_in[14];
    const float* W_out      = (const float*)d_in[15];
    const float* b_out      = (const float*)d_in[16];
    const float* ce         = (const float*)d_in[17];
    const float* le         = (const float*)d_in[18];
    const float* ln_g       = (const float*)d_in[19];
    const float* ln_b       = (const float*)d_in[20];
    float* out = (float*)d_out;

    k_inv<<<1, 32>>>(cam2ego);
    k_prep<<<(65536 + 147456 + NC * NL * CDIM + 255) / 256, 256>>>(W_val, W_off, W_attn, ce, le);
    k_proj<<<(NC * NQ + 255) / 256, 256>>>(means, intrins, post_rots, post_trans);
    k_offattn<<<dim3(100, 3), 256>>>(feature, b_off, b_attn);
    k_value<<<1386, 256>>>(feat0, feat1, feat2, b_val);
    k_gather<<<NQ, 256>>>();
    k_outln<<<NQ / 16, 256>>>(feature, W_out, b_out, ln_g, ln_b, out);
}